// round 15
// baseline (speedup 1.0000x reference)
#include <cuda_runtime.h>
#include <math.h>

#define BETA 0.1f

// One block per (b,p) tile, 256 threads, de-interleaved stores with
// DECOUPLED dependency chains:
//   - sx is published and __syncthreads() issued BEFORE the logf/mask chain,
//     so warps 4-7 (places writers, need only sx) start their 16 KB burst
//     immediately.
//   - warps 0-3 finish the Gumbel mask behind a named barrier scoped to
//     their 128 threads (bar.sync 1,128), then stream the sampled tile.
__global__ __launch_bounds__(256, 8)
void spatial_sampler_kernel(const float* __restrict__ x_cat,
                            const float* __restrict__ noise,
                            float* __restrict__ out,
                            long long half_elems)
{
    __shared__ float sx[128];   // [0:64) h row, [64:128) v row
    __shared__ float ss[128];   // masked rows (h part pre-scaled by 100)
    __shared__ float wmax[4];

    const int bp  = blockIdx.x;
    const int tid = threadIdx.x;

    const float* xrow = x_cat + (long long)bp * 128;
    const float* nrow = noise + (long long)bp * 128;

    float xv = 0.f, nv = 0.f;
    if (tid < 128) {
        xv = xrow[tid];
        nv = nrow[tid];
        sx[tid] = xv;               // publish sx as early as possible
    }
    __syncthreads();                // after this, places warps are unblocked

    if (tid >= 128) {
        // ---- warps 4-7: stream the places tile (depends only on sx) ----
        const int half_tid = tid & 127;
        const float4* v4 = reinterpret_cast<const float4*>(&sx[64]);
        float4* dst = reinterpret_cast<float4*>(out + (long long)bp * 4096);

        #pragma unroll
        for (int it = 0; it < 8; ++it) {
            const int i  = half_tid + it * 128;
            const int j  = i >> 4;
            const int c4 = i & 15;
            const float hj = sx[j];
            float4 vv = v4[c4];
            float4 o;
            o.x = hj * vv.x; o.y = hj * vv.y; o.z = hj * vv.z; o.w = hj * vv.w;
            dst[i] = o;
        }
    } else {
        // ---- warps 0-3: Gumbel mask, then stream the sampled tile ----
        const float lp = logf(xv) + BETA * nv;
        float m = lp;
        #pragma unroll
        for (int off = 16; off > 0; off >>= 1)
            m = fmaxf(m, __shfl_xor_sync(0xffffffffu, m, off));
        if ((tid & 31) == 0) wmax[tid >> 5] = m;
        asm volatile("bar.sync 1, 128;" ::: "memory");

        const float rowmax = (tid < 64) ? fmaxf(wmax[0], wmax[1])
                                        : fmaxf(wmax[2], wmax[3]);
        float s = (lp == rowmax) ? xv : 0.f;
        ss[tid] = (tid < 64) ? s * 100.0f : s;   // fold *100 into h half
        asm volatile("bar.sync 1, 128;" ::: "memory");

        const float4* v4 = reinterpret_cast<const float4*>(&ss[64]);
        float4* dst = reinterpret_cast<float4*>(out + half_elems
                                                + (long long)bp * 4096);
        #pragma unroll
        for (int it = 0; it < 8; ++it) {
            const int i  = tid + it * 128;
            const int j  = i >> 4;
            const int c4 = i & 15;
            const float hj = ss[j];
            float4 vv = v4[c4];
            float4 o;
            o.x = hj * vv.x; o.y = hj * vv.y; o.z = hj * vv.z; o.w = hj * vv.w;
            dst[i] = o;
        }
    }
}

extern "C" void kernel_launch(void* const* d_in, const int* in_sizes, int n_in,
                              void* d_out, int out_size)
{
    const float* x_cat = (const float*)d_in[0];
    const float* noise = (const float*)d_in[1];
    float* out = (float*)d_out;

    const long long half = (long long)out_size / 2;
    const int tiles = in_sizes[0] / 128;   // 8192 (b,p) tiles

    spatial_sampler_kernel<<<tiles, 256>>>(x_cat, noise, out, half);
}